// round 6
// baseline (speedup 1.0000x reference)
#include <cuda_runtime.h>
#include <cstdint>
#include <cstddef>

// Problem constants (fixed shapes)
#define Tn    1024
#define Bn    128
#define In    64
#define Hn    256
#define Cn    64
#define OUTL  128
#define KTOT  320          // In + Hn
#define NCTA  128
#define NTHR  256
#define RB    32           // batch rows per CTA
#define HB    8            // h-columns per CTA  -> 32 gate columns per CTA

// ---------------- persistent device state ----------------
__device__ float    g_hbuf[2][Bn][Hn];          // double-buffered hidden state
__device__ float    g_decH[Bn][OUTL][Hn];       // decoder hidden states for epilogue MLP
__device__ unsigned g_arrive = 0;               // monotonic arrival counter
__device__ unsigned g_phase  = 0;               // monotonic phase (barrier release)

__device__ __forceinline__ unsigned ld_acq_u32(const unsigned* p) {
    unsigned v;
    asm volatile("ld.acquire.gpu.u32 %0, [%1];" : "=r"(v) : "l"(p) : "memory");
    return v;
}

// Grid-wide sense barrier. All NCTA CTAs are co-resident (grid <= #SMs), so no deadlock.
__device__ __forceinline__ void grid_barrier(unsigned target) {
    __syncthreads();
    if (threadIdx.x == 0) {
        __threadfence();
        unsigned old = atomicAdd(&g_arrive, 1u);
        if ((old & (NCTA - 1u)) == (NCTA - 1u)) {
            asm volatile("red.release.gpu.global.add.u32 [%0], %1;"
                         :: "l"(&g_phase), "r"(1u) : "memory");
        } else {
            while ((int)(ld_acq_u32(&g_phase) - target) < 0) { }
        }
    }
    __syncthreads();
}

__device__ __forceinline__ float sigf(float x) {
    return 1.0f / (1.0f + __expf(-x));
}
__device__ __forceinline__ float tanhf_fast(float x) {
    // accurate to ~1e-7 rel; clamp avoids inf/inf
    x = fminf(fmaxf(x, -15.0f), 15.0f);
    float e = __expf(2.0f * x);
    return (e - 1.0f) / (e + 1.0f);
}

// 32-row x 32-gatecol tile GEMM: acc[ri] = bias + sum_k a[row][k]*w[k][lane]
template<int KSTART>
__device__ __forceinline__ void gemm_tile(const float* __restrict__ aS,
                                          const float* __restrict__ ws,
                                          int lane, int w, float biasv,
                                          float* __restrict__ acc)
{
    acc[0] = biasv; acc[1] = biasv; acc[2] = biasv; acc[3] = biasv;
    const float* a0 = aS + (w * 4 + 0) * KTOT;
    const float* a1 = aS + (w * 4 + 1) * KTOT;
    const float* a2 = aS + (w * 4 + 2) * KTOT;
    const float* a3 = aS + (w * 4 + 3) * KTOT;
    #pragma unroll 4
    for (int k = KSTART; k < KTOT; k += 4) {
        float w0 = ws[(k + 0) * 32 + lane];
        float w1 = ws[(k + 1) * 32 + lane];
        float w2 = ws[(k + 2) * 32 + lane];
        float w3 = ws[(k + 3) * 32 + lane];
        float4 A;
        A = *(const float4*)(a0 + k);
        acc[0] = fmaf(A.x, w0, fmaf(A.y, w1, fmaf(A.z, w2, fmaf(A.w, w3, acc[0]))));
        A = *(const float4*)(a1 + k);
        acc[1] = fmaf(A.x, w0, fmaf(A.y, w1, fmaf(A.z, w2, fmaf(A.w, w3, acc[1]))));
        A = *(const float4*)(a2 + k);
        acc[2] = fmaf(A.x, w0, fmaf(A.y, w1, fmaf(A.z, w2, fmaf(A.w, w3, acc[2]))));
        A = *(const float4*)(a3 + k);
        acc[3] = fmaf(A.x, w0, fmaf(A.y, w1, fmaf(A.z, w2, fmaf(A.w, w3, acc[3]))));
    }
}

// ---------------- persistent encoder + decoder kernel ----------------
extern "C" __global__ void __launch_bounds__(NTHR, 1)
lstm_persistent(const float* __restrict__ x, const int* __restrict__ lengths,
                const float* __restrict__ W_ih, const float* __restrict__ W_hh,
                const float* __restrict__ b_ih, const float* __restrict__ b_hh)
{
    extern __shared__ float sm[];
    float*    ws    = sm;                         // [KTOT][32] weights (k-major)
    float*    aS    = ws + KTOT * 32;             // [RB][KTOT] activations [x_t | h]
    float*    cS    = aS + RB * KTOT;             // [RB][HB]   cell state (CTA-private)
    int*      lenS  = (int*)(cS + RB * HB);       // [RB]
    unsigned* sbase = (unsigned*)(lenS + RB);     // [1] barrier base phase

    const int tid  = threadIdx.x;
    const int lane = tid & 31;
    const int w    = tid >> 5;
    const int jj   = lane & 7;        // h-col within CTA tile
    const int q    = lane >> 3;       // gate index 0..3 (i,f,g,o)
    const int rg   = blockIdx.x >> 5; // 0..3 row group
    const int cg   = blockIdx.x & 31; // 0..31 col group
    const int row0 = rg * RB;
    const int col0 = cg * HB;

    // Load weight tile into smem, k-major: ws[k*32 + l] with l -> gate col
    for (int idx = tid; idx < KTOT * 32; idx += NTHR) {
        int k = idx >> 5, l = idx & 31;
        int g = (l >> 3) * Hn + col0 + (l & 7);
        ws[idx] = (k < In) ? W_ih[g * In + k] : W_hh[g * Hn + (k - In)];
    }
    for (int idx = tid; idx < RB * HB; idx += NTHR) cS[idx] = 0.0f;
    if (tid < RB) lenS[tid] = lengths[row0 + tid];
    if (tid < RB * HB) g_hbuf[0][row0 + (tid >> 3)][col0 + (tid & 7)] = 0.0f;
    if (tid == 0) *sbase = ld_acq_u32(&g_phase);  // stable: nobody arrived yet
    __syncthreads();
    const unsigned base = *sbase;
    unsigned nb = 1;

    const int   g_lane = q * Hn + col0 + jj;
    const float biasv  = b_ih[g_lane] + b_hh[g_lane];

    grid_barrier(base + nb); ++nb;   // h0 zero-init visible chip-wide

    int   p = 0;
    float acc[4];

    // ============ encoder: 1024 steps ============
    for (int t = 0; t < Tn; ++t) {
        // stage h (L2-only loads: other CTAs wrote it last step)
        for (int idx = tid; idx < RB * (Hn / 4); idx += NTHR) {
            int r = idx >> 6, c4 = idx & 63;
            float4 v = __ldcg(((const float4*)&g_hbuf[p][row0 + r][0]) + c4);
            *(((float4*)(aS + r * KTOT + In)) + c4) = v;
        }
        // stage x_t (read-only, L1 cacheable)
        for (int idx = tid; idx < RB * (In / 4); idx += NTHR) {
            int r = idx >> 4, c4 = idx & 15;
            float4 v = *(((const float4*)(x + ((size_t)(row0 + r) * Tn + t) * In)) + c4);
            *(((float4*)(aS + r * KTOT)) + c4) = v;
        }
        __syncthreads();

        gemm_tile<0>(aS, ws, lane, w, biasv, acc);

        #pragma unroll
        for (int ri = 0; ri < 4; ++ri) {
            float gi = __shfl_sync(0xffffffffu, acc[ri], jj);
            float gf = __shfl_sync(0xffffffffu, acc[ri], jj + 8);
            float gg = __shfl_sync(0xffffffffu, acc[ri], jj + 16);
            float go = __shfl_sync(0xffffffffu, acc[ri], jj + 24);
            if (q == 0) {
                int   r    = w * 4 + ri;
                float cold = cS[r * HB + jj];
                float c2   = sigf(gf) * cold + sigf(gi) * tanhf_fast(gg);
                float h2   = sigf(go) * tanhf_fast(c2);
                if (t >= lenS[r]) {                     // length mask: freeze state
                    h2 = aS[r * KTOT + In + col0 + jj];
                    c2 = cold;
                }
                cS[r * HB + jj] = c2;
                g_hbuf[p ^ 1][row0 + r][col0 + jj] = h2;
            }
        }
        grid_barrier(base + nb); ++nb;
        p ^= 1;
    }

    // ============ decoder: 128 steps (gates_x = bias, no mask) ============
    for (int s = 0; s < OUTL; ++s) {
        for (int idx = tid; idx < RB * (Hn / 4); idx += NTHR) {
            int r = idx >> 6, c4 = idx & 63;
            float4 v = __ldcg(((const float4*)&g_hbuf[p][row0 + r][0]) + c4);
            *(((float4*)(aS + r * KTOT + In)) + c4) = v;
        }
        __syncthreads();

        gemm_tile<In>(aS, ws, lane, w, biasv, acc);

        #pragma unroll
        for (int ri = 0; ri < 4; ++ri) {
            float gi = __shfl_sync(0xffffffffu, acc[ri], jj);
            float gf = __shfl_sync(0xffffffffu, acc[ri], jj + 8);
            float gg = __shfl_sync(0xffffffffu, acc[ri], jj + 16);
            float go = __shfl_sync(0xffffffffu, acc[ri], jj + 24);
            if (q == 0) {
                int   r    = w * 4 + ri;
                float cold = cS[r * HB + jj];
                float c2   = sigf(gf) * cold + sigf(gi) * tanhf_fast(gg);
                float h2   = sigf(go) * tanhf_fast(c2);
                cS[r * HB + jj] = c2;
                g_hbuf[p ^ 1][row0 + r][col0 + jj] = h2;
                g_decH[row0 + r][s][col0 + jj] = h2;    // saved for epilogue MLP
            }
        }
        grid_barrier(base + nb); ++nb;
        p ^= 1;
    }
}

// ---------------- epilogue: out = relu(decH @ W1^T + b1) @ W2^T + b2 ----------------
// M = Bn*OUTL = 16384 rows, 32 rows per CTA -> 512 CTAs, fully parallel.
extern "C" __global__ void __launch_bounds__(256, 1)
mlp_epilogue(const float* __restrict__ W1, const float* __restrict__ b1,
             const float* __restrict__ W2, const float* __restrict__ b2,
             float* __restrict__ out)
{
    extern __shared__ float sm[];
    float* As = sm;            // [32][256] decoder h tile
    float* Hs = sm + 32 * 256; // [32][256] relu hidden tile

    const int tid  = threadIdx.x;
    const int lane = tid & 31;
    const int w    = tid >> 5;
    const int m0   = blockIdx.x * 32;

    const float* dh = &g_decH[0][0][0];   // flat: row m = b*OUTL + s, stride Hn
    for (int idx = tid; idx < 32 * (Hn / 4); idx += 256) {
        int r = idx >> 6, c4 = idx & 63;
        *(((float4*)(As + r * Hn)) + c4) =
            *(((const float4*)(dh + (size_t)(m0 + r) * Hn)) + c4);
    }
    __syncthreads();

    // hidden phase: warp w owns hidden cols [w*32, w*32+32), lane -> one col, 32 rows
    {
        const int h = w * 32 + lane;
        float acc[32];
        const float bv = b1[h];
        #pragma unroll
        for (int r = 0; r < 32; ++r) acc[r] = bv;
        for (int k = 0; k < Hn; k += 4) {
            float4 wv = *(const float4*)(W1 + (size_t)h * Hn + k);
            #pragma unroll
            for (int r = 0; r < 32; ++r) {
                float4 av = *(const float4*)(As + r * Hn + k);
                acc[r] = fmaf(av.x, wv.x, fmaf(av.y, wv.y,
                         fmaf(av.z, wv.z, fmaf(av.w, wv.w, acc[r]))));
            }
        }
        #pragma unroll
        for (int r = 0; r < 32; ++r) Hs[r * Hn + h] = fmaxf(acc[r], 0.0f);
    }
    __syncthreads();

    // out phase: warp w owns rows w*4..w*4+3; lane -> out cols {lane, lane+32}
    {
        float o[4][2];
        const float ba = b2[lane];
        const float bb = b2[lane + 32];
        #pragma unroll
        for (int ri = 0; ri < 4; ++ri) { o[ri][0] = ba; o[ri][1] = bb; }
        for (int k = 0; k < Hn; k += 4) {
            float4 wa = *(const float4*)(W2 + (size_t)lane * Hn + k);
            float4 wb = *(const float4*)(W2 + (size_t)(lane + 32) * Hn + k);
            #pragma unroll
            for (int ri = 0; ri < 4; ++ri) {
                float4 hv = *(const float4*)(Hs + (w * 4 + ri) * Hn + k);
                o[ri][0] = fmaf(hv.x, wa.x, fmaf(hv.y, wa.y,
                           fmaf(hv.z, wa.z, fmaf(hv.w, wa.w, o[ri][0]))));
                o[ri][1] = fmaf(hv.x, wb.x, fmaf(hv.y, wb.y,
                           fmaf(hv.z, wb.z, fmaf(hv.w, wb.w, o[ri][1]))));
            }
        }
        #pragma unroll
        for (int ri = 0; ri < 4; ++ri) {
            size_t m = (size_t)(m0 + w * 4 + ri);
            out[m * Cn + lane]      = o[ri][0];
            out[m * Cn + lane + 32] = o[ri][1];
        }
    }
}

// ---------------- launch ----------------
extern "C" void kernel_launch(void* const* d_in, const int* in_sizes, int n_in,
                              void* d_out, int out_size) {
    // input order: x, lengths, [out_lengths], W_ih, W_hh, b_ih, b_hh, W1, b1, W2, b2
    const int off = (n_in >= 11) ? 3 : 2;
    const float* x       = (const float*)d_in[0];
    const int*   lengths = (const int*)  d_in[1];
    const float* W_ih    = (const float*)d_in[off + 0];
    const float* W_hh    = (const float*)d_in[off + 1];
    const float* b_ih    = (const float*)d_in[off + 2];
    const float* b_hh    = (const float*)d_in[off + 3];
    const float* W1      = (const float*)d_in[off + 4];
    const float* b1      = (const float*)d_in[off + 5];
    const float* W2      = (const float*)d_in[off + 6];
    const float* b2      = (const float*)d_in[off + 7];
    float*       out     = (float*)d_out;

    const size_t smem1 = (size_t)(KTOT * 32 + RB * KTOT + RB * HB) * sizeof(float)
                       + RB * sizeof(int) + 16;                 // ~83 KB
    const size_t smem2 = (size_t)2 * 32 * Hn * sizeof(float);   // 64 KB

    cudaFuncSetAttribute(lstm_persistent,
                         cudaFuncAttributeMaxDynamicSharedMemorySize, (int)smem1);
    cudaFuncSetAttribute(mlp_epilogue,
                         cudaFuncAttributeMaxDynamicSharedMemorySize, (int)smem2);

    lstm_persistent<<<NCTA, NTHR, smem1>>>(x, lengths, W_ih, W_hh, b_ih, b_hh);
    mlp_epilogue<<<(Bn * OUTL) / 32, 256, smem2>>>(W1, b1, W2, b2, out);
}

// round 7
// speedup vs baseline: 1.4733x; 1.4733x over previous
#include <cuda_runtime.h>
#include <cstdint>
#include <cstddef>

// Problem constants (fixed shapes)
#define Tn    1024
#define Bn    128
#define In    64
#define Hn    256
#define Cn    64
#define OUTL  128
#define KT    320          // In + Hn
#define NCTA  128
#define NTHR  256
#define RB    32           // batch rows per CTA
#define HB    8            // h-columns per CTA -> 32 gate columns per CTA
#define PSTR  264          // partials row stride (floats), padded: conflict-free STS+LDS
#define KSL   40           // K-slice per warp (8 warps x 40 = 320)

typedef unsigned long long ull;

// ---------------- persistent device state ----------------
__device__ float g_hbuf[2][Bn][Hn];          // double-buffered hidden state
__device__ float g_decH[Bn][OUTL][Hn];       // decoder hidden states for epilogue MLP

struct alignas(128) PadCtr { unsigned v; unsigned pad[31]; };
__device__ PadCtr g_arrive[4];               // per row-group arrival counters
__device__ PadCtr g_phase[4];                // per row-group phase counters

// ---------------- small helpers ----------------
__device__ __forceinline__ unsigned ld_acq_u32(const unsigned* p) {
    unsigned v;
    asm volatile("ld.acquire.gpu.u32 %0, [%1];" : "=r"(v) : "l"(p) : "memory");
    return v;
}
__device__ __forceinline__ ull pk2(float x, float y) {
    ull r; asm("mov.b64 %0, {%1, %2};" : "=l"(r) : "f"(x), "f"(y)); return r;
}
__device__ __forceinline__ void upk2(ull v, float& x, float& y) {
    asm("mov.b64 {%0, %1}, %2;" : "=f"(x), "=f"(y) : "l"(v));
}
__device__ __forceinline__ ull ffma2(ull a, ull b, ull c) {
    ull d; asm("fma.rn.f32x2 %0, %1, %2, %3;" : "=l"(d) : "l"(a), "l"(b), "l"(c));
    return d;
}
__device__ __forceinline__ float sigf(float x) {
    return 1.0f / (1.0f + __expf(-x));
}
__device__ __forceinline__ float tanhf_fast(float x) {
    x = fminf(fmaxf(x, -15.0f), 15.0f);
    float e = __expf(2.0f * x);
    return (e - 1.0f) / (e + 1.0f);
}

// 32-CTA row-group barrier; all CTAs co-resident, monotonic phases (graph-replay safe)
__device__ __forceinline__ void group_barrier(int rg, unsigned target) {
    __syncthreads();
    if (threadIdx.x == 0) {
        __threadfence();
        unsigned old = atomicAdd(&g_arrive[rg].v, 1u);
        if ((old & 31u) == 31u) {
            asm volatile("red.release.gpu.global.add.u32 [%0], %1;"
                         :: "l"(&g_phase[rg].v), "r"(1u) : "memory");
        } else {
            while ((int)(ld_acq_u32(&g_phase[rg].v) - target) < 0) { }
        }
    }
    __syncthreads();
}

// ---------------- staging ----------------
__device__ __forceinline__ void stage_h(float* __restrict__ aS, int p, int row0, int tid) {
    #pragma unroll
    for (int it = 0; it < (RB * (Hn / 4)) / NTHR; ++it) {   // 8 iterations
        int idx = tid + it * NTHR;
        int r = idx >> 6, c4 = idx & 63;
        float4 v = __ldcg(((const float4*)&g_hbuf[p][row0 + r][0]) + c4);
        *(((float4*)(aS + r * KT + In)) + c4) = v;
    }
}
__device__ __forceinline__ void stage_x(float* __restrict__ aS, const float* __restrict__ x,
                                        int row0, int t, int tid) {
    #pragma unroll
    for (int it = 0; it < (RB * (In / 4)) / NTHR; ++it) {   // 2 iterations
        int idx = tid + it * NTHR;
        int r = idx >> 4, c4 = idx & 15;
        float4 v = *(((const float4*)(x + ((size_t)(row0 + r) * Tn + t) * In)) + c4);
        *(((float4*)(aS + r * KT)) + c4) = v;
    }
}

// ---------------- GEMM: each warp accumulates its 40-k slice from register weights ----
// partials -> part[r*PSTR + tid] (STS conflict-free: lanes consecutive)
__device__ __forceinline__ void gemm_part(const float* __restrict__ aS,
                                          float* __restrict__ part,
                                          const ull* __restrict__ wr2,
                                          int kbase, int tid)
{
    #pragma unroll 1
    for (int r0 = 0; r0 < RB; r0 += 4) {
        ull ac0 = 0ull, ac1 = 0ull, ac2 = 0ull, ac3 = 0ull;
        const float* p0 = aS + (r0 + 0) * KT + kbase;
        const float* p1 = aS + (r0 + 1) * KT + kbase;
        const float* p2 = aS + (r0 + 2) * KT + kbase;
        const float* p3 = aS + (r0 + 3) * KT + kbase;
        #pragma unroll
        for (int q4 = 0; q4 < KSL / 4; ++q4) {              // 10 iters, 4 k each
            ulonglong2 A;
            A = *(const ulonglong2*)(p0 + q4 * 4);
            ac0 = ffma2(A.x, wr2[2 * q4], ac0); ac0 = ffma2(A.y, wr2[2 * q4 + 1], ac0);
            A = *(const ulonglong2*)(p1 + q4 * 4);
            ac1 = ffma2(A.x, wr2[2 * q4], ac1); ac1 = ffma2(A.y, wr2[2 * q4 + 1], ac1);
            A = *(const ulonglong2*)(p2 + q4 * 4);
            ac2 = ffma2(A.x, wr2[2 * q4], ac2); ac2 = ffma2(A.y, wr2[2 * q4 + 1], ac2);
            A = *(const ulonglong2*)(p3 + q4 * 4);
            ac3 = ffma2(A.x, wr2[2 * q4], ac3); ac3 = ffma2(A.y, wr2[2 * q4 + 1], ac3);
        }
        float lo, hi;
        upk2(ac0, lo, hi); part[(r0 + 0) * PSTR + tid] = lo + hi;
        upk2(ac1, lo, hi); part[(r0 + 1) * PSTR + tid] = lo + hi;
        upk2(ac2, lo, hi); part[(r0 + 2) * PSTR + tid] = lo + hi;
        upk2(ac3, lo, hi); part[(r0 + 3) * PSTR + tid] = lo + hi;
    }
}

// ---------------- persistent encoder + decoder kernel ----------------
extern "C" __global__ void __launch_bounds__(NTHR, 1)
lstm_persistent(const float* __restrict__ x, const int* __restrict__ lengths,
                const float* __restrict__ W_ih, const float* __restrict__ W_hh,
                const float* __restrict__ b_ih, const float* __restrict__ b_hh)
{
    extern __shared__ float sm[];
    float* aS   = sm;                 // [RB][KT] activations [x_t | h]
    float* part = sm + RB * KT;       // [RB][PSTR] per-warp partial sums

    const int tid  = threadIdx.x;
    const int lane = tid & 31;
    const int w    = tid >> 5;
    const int rg   = blockIdx.x >> 5; // row group 0..3
    const int cg   = blockIdx.x & 31; // col group 0..31
    const int row0 = rg * RB;
    const int col0 = cg * HB;

    // ---- load this lane's weight slice into registers (once) ----
    const int grow  = (lane >> 3) * Hn + col0 + (lane & 7);  // gate row in W
    const int kbase = w * KSL;
    ull wr2[KSL / 2];
    {
        float wv[KSL];
        #pragma unroll
        for (int k = 0; k < KSL; ++k) {
            int kk = kbase + k;
            wv[k] = (kk < In) ? W_ih[(size_t)grow * In + kk]
                              : W_hh[(size_t)grow * Hn + (kk - In)];
        }
        #pragma unroll
        for (int i = 0; i < KSL / 2; ++i) wr2[i] = pk2(wv[2 * i], wv[2 * i + 1]);
    }

    // ---- update-role constants: thread owns (row ur, h-col uh) ----
    const int ur = tid >> 3, uh = tid & 7;
    float bq0, bq1, bq2, bq3;
    {
        int gl0 = 0 * Hn + col0 + uh, gl1 = 1 * Hn + col0 + uh;
        int gl2 = 2 * Hn + col0 + uh, gl3 = 3 * Hn + col0 + uh;
        bq0 = b_ih[gl0] + b_hh[gl0];
        bq1 = b_ih[gl1] + b_hh[gl1];
        bq2 = b_ih[gl2] + b_hh[gl2];
        bq3 = b_ih[gl3] + b_hh[gl3];
    }
    const int ulen = lengths[row0 + ur];
    float creg = 0.0f;                         // cell state lives in a register

    // x_0 prefetch + zero our h0 columns
    stage_x(aS, x, row0, 0, tid);
    g_hbuf[0][row0 + ur][col0 + uh] = 0.0f;

    unsigned base = 0;
    if (tid == 0) base = ld_acq_u32(&g_phase[rg].v);   // stable: no arrivals yet
    unsigned nb = 1;
    group_barrier(rg, base + nb); ++nb;                // h0 visible group-wide

    int p = 0;

    // ================= encoder: 1024 steps =================
    for (int t = 0; t < Tn; ++t) {
        stage_h(aS, p, row0, tid);
        __syncthreads();

        gemm_part(aS, part, wr2, kbase, tid);
        __syncthreads();

        // reduce 8 warp-partials + bias, cell update
        float g0 = bq0, g1 = bq1, g2 = bq2, g3 = bq3;
        #pragma unroll
        for (int ww = 0; ww < 8; ++ww) {
            const float* pr = part + ur * PSTR + ww * 32 + uh;
            g0 += pr[0]; g1 += pr[8]; g2 += pr[16]; g3 += pr[24];
        }
        float c2 = sigf(g1) * creg + sigf(g0) * tanhf_fast(g2);
        float h2 = sigf(g3) * tanhf_fast(c2);
        if (t >= ulen) {                               // length mask: freeze state
            h2 = aS[ur * KT + In + col0 + uh];
            c2 = creg;
        }
        creg = c2;
        g_hbuf[p ^ 1][row0 + ur][col0 + uh] = h2;

        if (t + 1 < Tn) stage_x(aS, x, row0, t + 1, tid);  // hide under barrier

        group_barrier(rg, base + nb); ++nb;
        p ^= 1;
    }

    // zero x region of aS: decoder has gates_x = bias only
    #pragma unroll
    for (int it = 0; it < (RB * (In / 4)) / NTHR; ++it) {
        int idx = tid + it * NTHR;
        int r = idx >> 4, c4 = idx & 15;
        *(((float4*)(aS + r * KT)) + c4) = make_float4(0.f, 0.f, 0.f, 0.f);
    }

    // ================= decoder: 128 steps =================
    for (int s = 0; s < OUTL; ++s) {
        stage_h(aS, p, row0, tid);
        __syncthreads();

        gemm_part(aS, part, wr2, kbase, tid);
        __syncthreads();

        float g0 = bq0, g1 = bq1, g2 = bq2, g3 = bq3;
        #pragma unroll
        for (int ww = 0; ww < 8; ++ww) {
            const float* pr = part + ur * PSTR + ww * 32 + uh;
            g0 += pr[0]; g1 += pr[8]; g2 += pr[16]; g3 += pr[24];
        }
        float c2 = sigf(g1) * creg + sigf(g0) * tanhf_fast(g2);
        float h2 = sigf(g3) * tanhf_fast(c2);
        creg = c2;
        g_hbuf[p ^ 1][row0 + ur][col0 + uh] = h2;
        g_decH[row0 + ur][s][col0 + uh] = h2;          // saved for epilogue MLP

        group_barrier(rg, base + nb); ++nb;
        p ^= 1;
    }
}

// ---------------- epilogue: out = relu(decH @ W1^T + b1) @ W2^T + b2 ----------------
// M = Bn*OUTL = 16384 rows, 32 rows per CTA -> 512 CTAs, fully parallel.
extern "C" __global__ void __launch_bounds__(256, 1)
mlp_epilogue(const float* __restrict__ W1, const float* __restrict__ b1,
             const float* __restrict__ W2, const float* __restrict__ b2,
             float* __restrict__ out)
{
    extern __shared__ float sm[];
    float* As = sm;            // [32][256] decoder h tile
    float* Hs = sm + 32 * 256; // [32][256] relu hidden tile

    const int tid  = threadIdx.x;
    const int lane = tid & 31;
    const int w    = tid >> 5;
    const int m0   = blockIdx.x * 32;

    const float* dh = &g_decH[0][0][0];   // flat: row m = b*OUTL + s, stride Hn
    for (int idx = tid; idx < 32 * (Hn / 4); idx += 256) {
        int r = idx >> 6, c4 = idx & 63;
        *(((float4*)(As + r * Hn)) + c4) =
            *(((const float4*)(dh + (size_t)(m0 + r) * Hn)) + c4);
    }
    __syncthreads();

    // hidden phase: warp w owns hidden cols [w*32, w*32+32), lane -> one col, 32 rows
    {
        const int h = w * 32 + lane;
        float acc[32];
        const float bv = b1[h];
        #pragma unroll
        for (int r = 0; r < 32; ++r) acc[r] = bv;
        for (int k = 0; k < Hn; k += 4) {
            float4 wv = *(const float4*)(W1 + (size_t)h * Hn + k);
            #pragma unroll
            for (int r = 0; r < 32; ++r) {
                float4 av = *(const float4*)(As + r * Hn + k);
                acc[r] = fmaf(av.x, wv.x, fmaf(av.y, wv.y,
                         fmaf(av.z, wv.z, fmaf(av.w, wv.w, acc[r]))));
            }
        }
        #pragma unroll
        for (int r = 0; r < 32; ++r) Hs[r * Hn + h] = fmaxf(acc[r], 0.0f);
    }
    __syncthreads();

    // out phase: warp w owns rows w*4..w*4+3; lane -> out cols {lane, lane+32}
    {
        float o[4][2];
        const float ba = b2[lane];
        const float bb = b2[lane + 32];
        #pragma unroll
        for (int ri = 0; ri < 4; ++ri) { o[ri][0] = ba; o[ri][1] = bb; }
        for (int k = 0; k < Hn; k += 4) {
            float4 wa = *(const float4*)(W2 + (size_t)lane * Hn + k);
            float4 wb = *(const float4*)(W2 + (size_t)(lane + 32) * Hn + k);
            #pragma unroll
            for (int ri = 0; ri < 4; ++ri) {
                float4 hv = *(const float4*)(Hs + (w * 4 + ri) * Hn + k);
                o[ri][0] = fmaf(hv.x, wa.x, fmaf(hv.y, wa.y,
                           fmaf(hv.z, wa.z, fmaf(hv.w, wa.w, o[ri][0]))));
                o[ri][1] = fmaf(hv.x, wb.x, fmaf(hv.y, wb.y,
                           fmaf(hv.z, wb.z, fmaf(hv.w, wb.w, o[ri][1]))));
            }
        }
        #pragma unroll
        for (int ri = 0; ri < 4; ++ri) {
            size_t m = (size_t)(m0 + w * 4 + ri);
            out[m * Cn + lane]      = o[ri][0];
            out[m * Cn + lane + 32] = o[ri][1];
        }
    }
}

// ---------------- launch ----------------
extern "C" void kernel_launch(void* const* d_in, const int* in_sizes, int n_in,
                              void* d_out, int out_size) {
    // input order: x, lengths, [out_lengths], W_ih, W_hh, b_ih, b_hh, W1, b1, W2, b2
    const int off = (n_in >= 11) ? 3 : 2;
    const float* x       = (const float*)d_in[0];
    const int*   lengths = (const int*)  d_in[1];
    const float* W_ih    = (const float*)d_in[off + 0];
    const float* W_hh    = (const float*)d_in[off + 1];
    const float* b_ih    = (const float*)d_in[off + 2];
    const float* b_hh    = (const float*)d_in[off + 3];
    const float* W1      = (const float*)d_in[off + 4];
    const float* b1      = (const float*)d_in[off + 5];
    const float* W2      = (const float*)d_in[off + 6];
    const float* b2      = (const float*)d_in[off + 7];
    float*       out     = (float*)d_out;

    const size_t smem1 = (size_t)(RB * KT + RB * PSTR) * sizeof(float);  // ~74.8 KB
    const size_t smem2 = (size_t)2 * 32 * Hn * sizeof(float);            // 64 KB

    cudaFuncSetAttribute(lstm_persistent,
                         cudaFuncAttributeMaxDynamicSharedMemorySize, (int)smem1);
    cudaFuncSetAttribute(mlp_epilogue,
                         cudaFuncAttributeMaxDynamicSharedMemorySize, (int)smem2);

    lstm_persistent<<<NCTA, NTHR, smem1>>>(x, lengths, W_ih, W_hh, b_ih, b_hh);
    mlp_epilogue<<<(Bn * OUTL) / 32, 256, smem2>>>(W1, b1, W2, b2, out);
}